// round 15
// baseline (speedup 1.0000x reference)
#include <cuda_runtime.h>
#include <cstdint>

// Screen tiling constants (match reference)
#define SW 1280
#define SH 720
#define TL 16
#define NBW 80           // ceil(1280/16)
#define NBH 45           // ceil(720/16)
#define NUM_BLOCK (NBW*NBH)   // 3600
#define N_POINTS 32768
#define NWORDS (N_POINTS / 32)   // 1024 bitmask words per tile-row

// Bit-packed separable masks: bit j of word w in row r = point (w*32+j) in row r.
// Total 500 KB -> L1/L2 resident, near-zero LTS read traffic in expand.
__device__ unsigned int g_bitsX[NBW * NWORDS];   // 320 KB
__device__ unsigned int g_bitsY[NBH * NWORDS];   // 180 KB

// ---------------------------------------------------------------------------
// Phase 1: each warp owns 32 consecutive points. Each lane computes its
// point's tile-index intervals once; then 80+45 __ballot_sync's produce one
// bitmask word per row, stored by lane 0. 1024 warps, ~125 ballots each.
// ---------------------------------------------------------------------------
__global__ void build_masks_kernel(const float* __restrict__ pos2d,
                                   const float* __restrict__ radius)
{
    int n    = blockIdx.x * blockDim.x + threadIdx.x;   // point id (= lane-aligned)
    int wi   = n >> 5;                                  // global warp / word index
    int lane = n & 31;

    float px = pos2d[2 * n + 0];
    float py = pos2d[2 * n + 1];
    float r  = radius[n];

    // Match reference exactly: clip to [0, W]/[0, H] then truncate to int32.
    int xmin = (int)fminf(fmaxf(px - r, 0.0f), (float)SW);
    int xmax = (int)fminf(fmaxf(px + r, 0.0f), (float)SW);
    int ymin = (int)fminf(fmaxf(py - r, 0.0f), (float)SH);
    int ymax = (int)fminf(fmaxf(py + r, 0.0f), (float)SH);

    // Tile edges are exact multiples of 16 (no screen-edge clamping needed):
    //   in_mask <=> xi in [xmin>>4, (xmax+15)>>4)   when xmax > xmin
    int x0 = xmin >> 4;
    int x1 = (xmax + 15) >> 4;
    if (xmax <= xmin) x1 = x0;          // degenerate AABB -> empty
    int y0 = ymin >> 4;
    int y1 = (ymax + 15) >> 4;
    if (ymax <= ymin) y1 = y0;

    #pragma unroll
    for (int xi = 0; xi < NBW; xi++) {
        unsigned int w = __ballot_sync(0xffffffffu, (xi >= x0) & (xi < x1));
        if (lane == 0) g_bitsX[xi * NWORDS + wi] = w;
    }
    #pragma unroll
    for (int yi = 0; yi < NBH; yi++) {
        unsigned int w = __ballot_sync(0xffffffffu, (yi >= y0) & (yi < y1));
        if (lane == 0) g_bitsY[yi * NWORDS + wi] = w;
    }
}

// ---------------------------------------------------------------------------
// Phase 2: out[t*N + n] = float(bitX[t/45][n] & bitY[t%45][n]).
// 8 CONSECUTIVE points per thread, ONE 256-bit store (st.global.cs.v8.b32,
// sm_100+): a warp's single STG.256 covers a contiguous 1024 B — fully
// coalesced (unlike R12's two strided 16B stores). Halves store & load
// instruction count vs R13. Per thread: one bitmask word pair (4 threads
// broadcast-share each word), extract 8 bits, spread nibbles -> 0x00/0x01
// bytes (IMAD 0x00204081 + AND 0x01010101), PRMT+IMAD -> f32 bit patterns.
// grid = (32768/(256*8)=16, 3600), block = 256.
// ---------------------------------------------------------------------------
__global__ void __launch_bounds__(256, 8)
expand_kernel(float* __restrict__ out)
{
    const int t  = blockIdx.y;                // tile id, 0..3599
    const int n8 = (blockIdx.x * blockDim.x + threadIdx.x) * 8;  // first point

    int xi = t / NBH;
    int yi = t - xi * NBH;

    unsigned int wx = __ldg(&g_bitsX[xi * NWORDS + (n8 >> 5)]);
    unsigned int wy = __ldg(&g_bitsY[yi * NWORDS + (n8 >> 5)]);
    unsigned int bits = ((wx & wy) >> (n8 & 31)) & 0xFFu;   // 8 points' bits

    // Spread each nibble -> one 0x00/0x01 byte per point
    unsigned int m0 = ((bits & 0xFu) * 0x00204081u) & 0x01010101u;  // pts 0..3
    unsigned int m1 = ((bits >> 4)   * 0x00204081u) & 0x01010101u;  // pts 4..7

    const unsigned int ONE = 0x3f800000u;     // bit pattern of 1.0f

    unsigned int r0 = __byte_perm(m0, 0u, 0x4440) * ONE;
    unsigned int r1 = __byte_perm(m0, 0u, 0x4441) * ONE;
    unsigned int r2 = __byte_perm(m0, 0u, 0x4442) * ONE;
    unsigned int r3 = __byte_perm(m0, 0u, 0x4443) * ONE;
    unsigned int r4 = __byte_perm(m1, 0u, 0x4440) * ONE;
    unsigned int r5 = __byte_perm(m1, 0u, 0x4441) * ONE;
    unsigned int r6 = __byte_perm(m1, 0u, 0x4442) * ONE;
    unsigned int r7 = __byte_perm(m1, 0u, 0x4443) * ONE;

    // 32-byte aligned: byte offset = 4*(t*32768 + n8), n8 multiple of 8.
    float* p = out + (size_t)t * N_POINTS + n8;
    asm volatile(
        "st.global.cs.v8.b32 [%0], {%1, %2, %3, %4, %5, %6, %7, %8};"
        :: "l"(p), "r"(r0), "r"(r1), "r"(r2), "r"(r3),
           "r"(r4), "r"(r5), "r"(r6), "r"(r7)
        : "memory");
}

extern "C" void kernel_launch(void* const* d_in, const int* in_sizes, int n_in,
                              void* d_out, int out_size)
{
    const float* pos2d  = (const float*)d_in[0];
    const float* radius = (const float*)d_in[1];
    float* out          = (float*)d_out;

    build_masks_kernel<<<N_POINTS / 256, 256>>>(pos2d, radius);

    dim3 grid(N_POINTS / (256 * 8), NUM_BLOCK);   // (16, 3600)
    expand_kernel<<<grid, 256>>>(out);
}